// round 1
// baseline (speedup 1.0000x reference)
#include <cuda_runtime.h>

// Problem constants
#define BC_C   9
#define BC_FR  64
#define BC_T   64
#define BC_P   4
#define BC_E   192
#define BC_NF  16
#define BC_NT  16

using u64 = unsigned long long;

__device__ __forceinline__ u64 pack2(float lo, float hi) {
    u64 r;
    asm("mov.b64 %0, {%1, %2};" : "=l"(r) : "f"(lo), "f"(hi));
    return r;
}
__device__ __forceinline__ void unpack2(u64 v, float& lo, float& hi) {
    asm("mov.b64 {%0, %1}, %2;" : "=f"(lo), "=f"(hi) : "l"(v));
}
// d = a * b + d  on packed f32x2 (Blackwell FFMA2 — only reachable via PTX)
__device__ __forceinline__ void fma2(u64& d, u64 a, u64 b) {
    asm("fma.rn.f32x2 %0, %1, %2, %0;" : "+l"(d) : "l"(a), "l"(b));
}

// Grid: (NF=16, C=9, B). Block: 192 threads.
//   q = tid % 48  -> e-quad (e = 4q .. 4q+3)
//   g = tid / 48  -> t-group, thread handles t = 4g .. 4g+3
// Each thread computes 16 outputs (4 e x 4 t) with W resident in registers.
__global__ __launch_bounds__(192, 2)
void patch_embed_kernel(const float* __restrict__ x,
                        const float* __restrict__ W,
                        const float* __restrict__ bvec,
                        const float* __restrict__ chEmb,
                        const float* __restrict__ spEmb,
                        const float* __restrict__ timePos,
                        const float* __restrict__ freqPos,
                        const int*   __restrict__ spIdx,
                        float* __restrict__ out)
{
    const int f   = blockIdx.x;   // 0..15
    const int c   = blockIdx.y;   // 0..8
    const int b   = blockIdx.z;   // 0..B-1
    const int tid = threadIdx.x;  // 0..191
    const int q   = tid % 48;
    const int g   = tid / 48;
    const int e0  = q * 4;

    // 4 input rows (f*4 .. f*4+3) are 256 contiguous floats — stage into smem.
    __shared__ __align__(16) float xs[256];
    const float4* gx = reinterpret_cast<const float4*>(
        x + ((size_t)(b * BC_C + c) * BC_FR + (size_t)f * BC_P) * BC_T);
    if (tid < 64) reinterpret_cast<float4*>(xs)[tid] = gx[tid];

    // W for 4 consecutive e rows: 64 floats = 32 packed f32x2 in registers.
    // Pair k within a row covers (u = k/2, v = 2*(k%2)), matching x pairs.
    u64 w[32];
    {
        const ulonglong2* wp = reinterpret_cast<const ulonglong2*>(W + e0 * 16);
        #pragma unroll
        for (int i = 0; i < 16; i++) {
            ulonglong2 v = __ldg(wp + i);
            w[2 * i]     = v.x;
            w[2 * i + 1] = v.y;
        }
    }

    // Per-e base bias: b + channel + spatial[spatial_idx[c]] + freq_pos[f]
    const int sidx = __ldg(spIdx + c);
    float4 bb = *reinterpret_cast<const float4*>(bvec + e0);
    float4 ce = *reinterpret_cast<const float4*>(chEmb   + c * BC_E + e0);
    float4 se = *reinterpret_cast<const float4*>(spEmb   + sidx * BC_E + e0);
    float4 fe = *reinterpret_cast<const float4*>(freqPos + f * BC_E + e0);
    float4 base;
    base.x = bb.x + ce.x + se.x + fe.x;
    base.y = bb.y + ce.y + se.y + fe.y;
    base.z = bb.z + ce.z + se.z + fe.z;
    base.w = bb.w + ce.w + se.w + fe.w;

    __syncthreads();

    float* outp = out + ((size_t)b * (BC_C * BC_NF * BC_NT)
                         + c * (BC_NF * BC_NT) + f * BC_NT) * BC_E;

    #pragma unroll
    for (int i = 0; i < 4; i++) {
        const int t = g * 4 + i;

        // Patch x values: 4 rows x 4 cols. Each float4 row-chunk is already
        // two correctly packed f32x2 pairs — zero packing cost.
        u64 xp[8];
        #pragma unroll
        for (int u = 0; u < 4; u++) {
            ulonglong2 v = *reinterpret_cast<const ulonglong2*>(&xs[u * 64 + t * 4]);
            xp[2 * u]     = v.x;
            xp[2 * u + 1] = v.y;
        }

        float4 tp = *reinterpret_cast<const float4*>(timePos + t * BC_E + e0);

        u64 acc0 = pack2(base.x + tp.x, 0.0f);
        u64 acc1 = pack2(base.y + tp.y, 0.0f);
        u64 acc2 = pack2(base.z + tp.z, 0.0f);
        u64 acc3 = pack2(base.w + tp.w, 0.0f);

        #pragma unroll
        for (int k = 0; k < 8; k++) {
            fma2(acc0, xp[k], w[k]);
            fma2(acc1, xp[k], w[8 + k]);
            fma2(acc2, xp[k], w[16 + k]);
            fma2(acc3, xp[k], w[24 + k]);
        }

        float4 r;
        { float lo, hi; unpack2(acc0, lo, hi); r.x = lo + hi; }
        { float lo, hi; unpack2(acc1, lo, hi); r.y = lo + hi; }
        { float lo, hi; unpack2(acc2, lo, hi); r.z = lo + hi; }
        { float lo, hi; unpack2(acc3, lo, hi); r.w = lo + hi; }

        *reinterpret_cast<float4*>(outp + t * BC_E + e0) = r;
    }
}

extern "C" void kernel_launch(void* const* d_in, const int* in_sizes, int n_in,
                              void* d_out, int out_size)
{
    const float* x    = (const float*)d_in[0];
    const float* W    = (const float*)d_in[1];
    const float* bv   = (const float*)d_in[2];
    const float* ch   = (const float*)d_in[3];
    const float* sp   = (const float*)d_in[4];
    const float* tpos = (const float*)d_in[5];
    const float* fpos = (const float*)d_in[6];
    const int*   sidx = (const int*)d_in[7];
    float* out = (float*)d_out;

    const int Bx = in_sizes[0] / (BC_C * BC_FR * BC_T);

    dim3 grid(BC_NF, BC_C, Bx);
    patch_embed_kernel<<<grid, 192>>>(x, W, bv, ch, sp, tpos, fpos, sidx, out);
}

// round 2
// speedup vs baseline: 4.2245x; 4.2245x over previous
#include <cuda_runtime.h>

// Problem constants
#define BC_C   9
#define BC_FR  64
#define BC_T   64
#define BC_P   4
#define BC_E   192
#define BC_NF  16
#define BC_NT  16

using u64 = unsigned long long;

__device__ __forceinline__ u64 pack2(float lo, float hi) {
    u64 r;
    asm("mov.b64 %0, {%1, %2};" : "=l"(r) : "f"(lo), "f"(hi));
    return r;
}
__device__ __forceinline__ void unpack2(u64 v, float& lo, float& hi) {
    asm("mov.b64 {%0, %1}, %2;" : "=f"(lo), "=f"(hi) : "l"(v));
}
// d = a * b + d  on packed f32x2 (Blackwell FFMA2 — only reachable via PTX)
__device__ __forceinline__ void fma2(u64& d, u64 a, u64 b) {
    asm("fma.rn.f32x2 %0, %1, %2, %0;" : "+l"(d) : "l"(a), "l"(b));
}

// Grid: (C=9, B). Block: 192 threads. One block handles the full 64x64
// time-freq plane of one (b, c): 16 f-tiles x 16 t-tiles x 192 e.
//   q = tid % 48  -> e-quad (e = 4q .. 4q+3); W for these 4 e rows lives in regs
//   g = tid / 48  -> f-group, thread handles f = 4g .. 4g+3 (all 16 t each)
// W is loaded ONCE per block and reused for 64 output-quads per thread
// (16x more reuse than the previous per-(b,c,f) grid — W's lane-divergent
// LDG wavefronts were 80% of L1 traffic).
__global__ __launch_bounds__(192, 2)
void patch_embed_kernel(const float* __restrict__ x,
                        const float* __restrict__ W,
                        const float* __restrict__ bvec,
                        const float* __restrict__ chEmb,
                        const float* __restrict__ spEmb,
                        const float* __restrict__ timePos,
                        const float* __restrict__ freqPos,
                        const int*   __restrict__ spIdx,
                        float* __restrict__ out)
{
    const int c   = blockIdx.x;   // 0..8
    const int b   = blockIdx.y;   // 0..B-1
    const int tid = threadIdx.x;  // 0..191
    const int q   = tid % 48;
    const int g   = tid / 48;     // 0..3
    const int e0  = q * 4;

    // Stage the whole 64x64 input plane for this (b,c): 16 KB, coalesced.
    __shared__ __align__(16) float xs[BC_FR * BC_T];
    {
        const float4* gx = reinterpret_cast<const float4*>(
            x + (size_t)(b * BC_C + c) * (BC_FR * BC_T));
        float4* sx = reinterpret_cast<float4*>(xs);
        #pragma unroll
        for (int i = tid; i < (BC_FR * BC_T) / 4; i += 192)
            sx[i] = gx[i];
    }

    // W for 4 consecutive e rows: 64 floats = 32 packed f32x2 in registers.
    // Pair k within a row covers (u = k/2, v = 2*(k%2)), matching x pairs.
    u64 w[32];
    {
        const ulonglong2* wp = reinterpret_cast<const ulonglong2*>(W + e0 * 16);
        #pragma unroll
        for (int i = 0; i < 16; i++) {
            ulonglong2 v = __ldg(wp + i);
            w[2 * i]     = v.x;
            w[2 * i + 1] = v.y;
        }
    }

    // Per-e static bias: b + channel + spatial[spatial_idx[c]]  (f-independent part)
    const int sidx = __ldg(spIdx + c);
    float4 bb = *reinterpret_cast<const float4*>(bvec + e0);
    float4 ce = *reinterpret_cast<const float4*>(chEmb + c * BC_E + e0);
    float4 se = *reinterpret_cast<const float4*>(spEmb + sidx * BC_E + e0);
    float4 bs;
    bs.x = bb.x + ce.x + se.x;
    bs.y = bb.y + ce.y + se.y;
    bs.z = bb.z + ce.z + se.z;
    bs.w = bb.w + ce.w + se.w;

    // Per-f base = static + freq_pos[f], for this thread's 4 f values.
    float4 base[4];
    #pragma unroll
    for (int fi = 0; fi < 4; fi++) {
        const int f = g * 4 + fi;
        float4 fe = *reinterpret_cast<const float4*>(freqPos + f * BC_E + e0);
        base[fi].x = bs.x + fe.x;
        base[fi].y = bs.y + fe.y;
        base[fi].z = bs.z + fe.z;
        base[fi].w = bs.w + fe.w;
    }

    __syncthreads();

    float* outp = out + ((size_t)b * (BC_C * BC_NF * BC_NT)
                         + c * (BC_NF * BC_NT)) * BC_E;

    #pragma unroll 1
    for (int t = 0; t < BC_NT; t++) {
        // time pos for this t (L1-hot, coalesced across the warp)
        float4 tp = *reinterpret_cast<const float4*>(timePos + t * BC_E + e0);

        #pragma unroll
        for (int fi = 0; fi < 4; fi++) {
            const int f = g * 4 + fi;

            // Patch x values: 4 rows x 4 cols. Each 16B row-chunk is already
            // two correctly packed f32x2 pairs — and broadcast across the
            // warp (all lanes share (f,t)) so LDS is ~1 wavefront each.
            u64 xp[8];
            #pragma unroll
            for (int u = 0; u < 4; u++) {
                ulonglong2 v = *reinterpret_cast<const ulonglong2*>(
                    &xs[(f * 4 + u) * BC_T + t * 4]);
                xp[2 * u]     = v.x;
                xp[2 * u + 1] = v.y;
            }

            u64 acc0 = pack2(base[fi].x + tp.x, 0.0f);
            u64 acc1 = pack2(base[fi].y + tp.y, 0.0f);
            u64 acc2 = pack2(base[fi].z + tp.z, 0.0f);
            u64 acc3 = pack2(base[fi].w + tp.w, 0.0f);

            #pragma unroll
            for (int k = 0; k < 8; k++) {
                fma2(acc0, xp[k], w[k]);
                fma2(acc1, xp[k], w[8 + k]);
                fma2(acc2, xp[k], w[16 + k]);
                fma2(acc3, xp[k], w[24 + k]);
            }

            float4 r;
            { float lo, hi; unpack2(acc0, lo, hi); r.x = lo + hi; }
            { float lo, hi; unpack2(acc1, lo, hi); r.y = lo + hi; }
            { float lo, hi; unpack2(acc2, lo, hi); r.z = lo + hi; }
            { float lo, hi; unpack2(acc3, lo, hi); r.w = lo + hi; }

            *reinterpret_cast<float4*>(
                outp + (size_t)(f * BC_NT + t) * BC_E + e0) = r;
        }
    }
}

extern "C" void kernel_launch(void* const* d_in, const int* in_sizes, int n_in,
                              void* d_out, int out_size)
{
    const float* x    = (const float*)d_in[0];
    const float* W    = (const float*)d_in[1];
    const float* bv   = (const float*)d_in[2];
    const float* ch   = (const float*)d_in[3];
    const float* sp   = (const float*)d_in[4];
    const float* tpos = (const float*)d_in[5];
    const float* fpos = (const float*)d_in[6];
    const int*   sidx = (const int*)d_in[7];
    float* out = (float*)d_out;

    const int Bx = in_sizes[0] / (BC_C * BC_FR * BC_T);

    dim3 grid(BC_C, Bx);
    patch_embed_kernel<<<grid, 192>>>(x, W, bv, ch, sp, tpos, fpos, sidx, out);
}

// round 3
// speedup vs baseline: 4.9209x; 1.1648x over previous
#include <cuda_runtime.h>

// Problem constants
#define BC_C   9
#define BC_FR  64
#define BC_T   64
#define BC_P   4
#define BC_E   192
#define BC_NF  16
#define BC_NT  16

#define W_ROW_PAD 68   // 64 floats of W per e-quad + 4 pad -> conflict-free LDS.128

using u64 = unsigned long long;

__device__ __forceinline__ u64 pack2(float lo, float hi) {
    u64 r;
    asm("mov.b64 %0, {%1, %2};" : "=l"(r) : "f"(lo), "f"(hi));
    return r;
}
__device__ __forceinline__ void unpack2(u64 v, float& lo, float& hi) {
    asm("mov.b64 {%0, %1}, %2;" : "=f"(lo), "=f"(hi) : "l"(v));
}
// d = a * b + d  on packed f32x2 (Blackwell FFMA2 — only reachable via PTX)
__device__ __forceinline__ void fma2(u64& d, u64 a, u64 b) {
    asm("fma.rn.f32x2 %0, %1, %2, %0;" : "+l"(d) : "l"(a), "l"(b));
}

// Grid: (C=9, B). Block: 192 threads. One block = full 64x64 plane of one (b,c).
//   q = tid % 48 -> e-quad (e = 4q..4q+3), W for these 4 e rows ends up in regs
//   g = tid / 48 -> f-group: f = 4g..4g+3, all 16 t each
// W is staged GMEM->SMEM coalesced, then read via conflict-free padded LDS.128
// (the previous lane-divergent W LDG cost ~48K L1 cycles/SM — 25% of runtime).
__global__ __launch_bounds__(192, 2)
void patch_embed_kernel(const float* __restrict__ x,
                        const float* __restrict__ W,
                        const float* __restrict__ bvec,
                        const float* __restrict__ chEmb,
                        const float* __restrict__ spEmb,
                        const float* __restrict__ timePos,
                        const float* __restrict__ freqPos,
                        const int*   __restrict__ spIdx,
                        float* __restrict__ out)
{
    const int c   = blockIdx.x;   // 0..8
    const int b   = blockIdx.y;   // 0..B-1
    const int tid = threadIdx.x;  // 0..191
    const int q   = tid % 48;
    const int g   = tid / 48;     // 0..3
    const int e0  = q * 4;

    __shared__ __align__(16) float xs[BC_FR * BC_T];          // 16 KB input plane
    __shared__ __align__(16) float ws[48 * W_ROW_PAD];        // ~13 KB padded W

    // Stage x plane (coalesced float4).
    {
        const float4* gx = reinterpret_cast<const float4*>(
            x + (size_t)(b * BC_C + c) * (BC_FR * BC_T));
        float4* sx = reinterpret_cast<float4*>(xs);
        #pragma unroll
        for (int i = tid; i < (BC_FR * BC_T) / 4; i += 192)
            sx[i] = gx[i];
    }

    // Stage W (3072 floats) coalesced into padded smem: global float4 j ->
    // row r = j/16 (e-quad), col = (j%16)*4 within the 64-float row.
    {
        const float4* gw = reinterpret_cast<const float4*>(W);
        #pragma unroll
        for (int j = tid; j < (BC_E * 16) / 4; j += 192) {
            int r   = j >> 4;          // e-quad row (0..47)
            int col = (j & 15) << 2;   // float offset within row
            *reinterpret_cast<float4*>(&ws[r * W_ROW_PAD + col]) = gw[j];
        }
    }

    // Per-e static bias: b + channel + spatial[spatial_idx[c]]
    const int sidx = __ldg(spIdx + c);
    float4 bb = *reinterpret_cast<const float4*>(bvec + e0);
    float4 ce = *reinterpret_cast<const float4*>(chEmb + c * BC_E + e0);
    float4 se = *reinterpret_cast<const float4*>(spEmb + sidx * BC_E + e0);
    float4 bs;
    bs.x = bb.x + ce.x + se.x;
    bs.y = bb.y + ce.y + se.y;
    bs.z = bb.z + ce.z + se.z;
    bs.w = bb.w + ce.w + se.w;

    // Per-f base = static + freq_pos[f], for this thread's 4 f values.
    float4 base[4];
    #pragma unroll
    for (int fi = 0; fi < 4; fi++) {
        const int f = g * 4 + fi;
        float4 fe = *reinterpret_cast<const float4*>(freqPos + f * BC_E + e0);
        base[fi].x = bs.x + fe.x;
        base[fi].y = bs.y + fe.y;
        base[fi].z = bs.z + fe.z;
        base[fi].w = bs.w + fe.w;
    }

    __syncthreads();

    // Pull W for this thread's 4 e rows into registers from padded smem.
    // Lane q reads ws[q*68 + i*4]: per 8-lane phase banks are 4*q mod 32 —
    // all distinct -> conflict-free LDS.128.
    u64 w[32];
    #pragma unroll
    for (int i = 0; i < 16; i++) {
        float4 v = *reinterpret_cast<const float4*>(&ws[q * W_ROW_PAD + i * 4]);
        w[2 * i]     = pack2(v.x, v.y);
        w[2 * i + 1] = pack2(v.z, v.w);
    }

    float* outp = out + ((size_t)b * (BC_C * BC_NF * BC_NT)
                         + c * (BC_NF * BC_NT)) * BC_E;

    // t unrolled by 2: 8 independent FMA2 chains per fi iteration.
    #pragma unroll 1
    for (int t = 0; t < BC_NT; t += 2) {
        float4 tp0 = *reinterpret_cast<const float4*>(timePos + t * BC_E + e0);
        float4 tp1 = *reinterpret_cast<const float4*>(timePos + (t + 1) * BC_E + e0);

        #pragma unroll
        for (int fi = 0; fi < 4; fi++) {
            const int f = g * 4 + fi;

            // Patch x for t and t+1: broadcast LDS (all lanes share (f,t)).
            u64 xp0[8], xp1[8];
            #pragma unroll
            for (int u = 0; u < 4; u++) {
                const float* rowp = &xs[(f * 4 + u) * BC_T];
                ulonglong2 v0 = *reinterpret_cast<const ulonglong2*>(rowp + t * 4);
                ulonglong2 v1 = *reinterpret_cast<const ulonglong2*>(rowp + (t + 1) * 4);
                xp0[2 * u] = v0.x;  xp0[2 * u + 1] = v0.y;
                xp1[2 * u] = v1.x;  xp1[2 * u + 1] = v1.y;
            }

            u64 a0 = pack2(base[fi].x + tp0.x, 0.0f);
            u64 a1 = pack2(base[fi].y + tp0.y, 0.0f);
            u64 a2 = pack2(base[fi].z + tp0.z, 0.0f);
            u64 a3 = pack2(base[fi].w + tp0.w, 0.0f);
            u64 b0 = pack2(base[fi].x + tp1.x, 0.0f);
            u64 b1 = pack2(base[fi].y + tp1.y, 0.0f);
            u64 b2 = pack2(base[fi].z + tp1.z, 0.0f);
            u64 b3 = pack2(base[fi].w + tp1.w, 0.0f);

            #pragma unroll
            for (int k = 0; k < 8; k++) {
                fma2(a0, xp0[k], w[k]);
                fma2(a1, xp0[k], w[8 + k]);
                fma2(a2, xp0[k], w[16 + k]);
                fma2(a3, xp0[k], w[24 + k]);
                fma2(b0, xp1[k], w[k]);
                fma2(b1, xp1[k], w[8 + k]);
                fma2(b2, xp1[k], w[16 + k]);
                fma2(b3, xp1[k], w[24 + k]);
            }

            float4 r0, r1;
            { float lo, hi; unpack2(a0, lo, hi); r0.x = lo + hi; }
            { float lo, hi; unpack2(a1, lo, hi); r0.y = lo + hi; }
            { float lo, hi; unpack2(a2, lo, hi); r0.z = lo + hi; }
            { float lo, hi; unpack2(a3, lo, hi); r0.w = lo + hi; }
            { float lo, hi; unpack2(b0, lo, hi); r1.x = lo + hi; }
            { float lo, hi; unpack2(b1, lo, hi); r1.y = lo + hi; }
            { float lo, hi; unpack2(b2, lo, hi); r1.z = lo + hi; }
            { float lo, hi; unpack2(b3, lo, hi); r1.w = lo + hi; }

            float* op = outp + (size_t)(f * BC_NT + t) * BC_E + e0;
            *reinterpret_cast<float4*>(op)        = r0;
            *reinterpret_cast<float4*>(op + BC_E) = r1;
        }
    }
}

extern "C" void kernel_launch(void* const* d_in, const int* in_sizes, int n_in,
                              void* d_out, int out_size)
{
    const float* x    = (const float*)d_in[0];
    const float* W    = (const float*)d_in[1];
    const float* bv   = (const float*)d_in[2];
    const float* ch   = (const float*)d_in[3];
    const float* sp   = (const float*)d_in[4];
    const float* tpos = (const float*)d_in[5];
    const float* fpos = (const float*)d_in[6];
    const int*   sidx = (const int*)d_in[7];
    float* out = (float*)d_out;

    const int Bx = in_sizes[0] / (BC_C * BC_FR * BC_T);

    dim3 grid(BC_C, Bx);
    patch_embed_kernel<<<grid, 192>>>(x, W, bv, ch, sp, tpos, fpos, sidx, out);
}